// round 13
// baseline (speedup 1.0000x reference)
#include <cuda_runtime.h>
#include <cuda_fp16.h>
#include <cstdint>

#define C_IN   128
#define C_OUT  256
#define TAPS   4
#define N_MAX  262144
#define PADN_MAX (N_MAX + TAPS * 128)
#define BN_EPS 1e-4f
#define STAGE_B 8192               // one A or B stage: 128 rows x 64 bytes (32 fp16)

// ---------------- device scratch ----------------
__device__ __half g_scratch[(size_t)PADN_MAX * C_OUT];  // contributions, fp16, perm order
__device__ __half g_xh[(size_t)N_MAX * C_IN];           // x converted to fp16
__device__ __half g_Bth[TAPS * C_OUT * C_IN];           // W as [tap][n][k], fp16
__device__ int   g_pslot[N_MAX * TAPS];                 // pslot[site*4+tap] = perm pos or -1
__device__ int   g_perm[PADN_MAX];                      // perm position -> input row
__device__ int   g_tap_count[TAPS];
__device__ int   g_pad_base[TAPS + 1];
__device__ int   g_tap_cursor[TAPS];
__device__ int   g_ctr;                                 // prep completion counter
__device__ float g_sum[C_OUT];
__device__ float g_sumsq[C_OUT];
__device__ float g_cnt;
__device__ float g_scale[C_OUT];
__device__ float g_bias[C_OUT];

// ---------------- helpers ----------------
__device__ __forceinline__ uint32_t smem_u32(const void* p) {
    uint32_t a;
    asm("{ .reg .u64 t; cvta.to.shared.u64 t, %1; cvt.u32.u64 %0, t; }" : "=r"(a) : "l"(p));
    return a;
}

#define CP_ASYNC(sa, ga) \
    asm volatile("cp.async.cg.shared.global [%0], [%1], 16;" :: "r"(sa), "l"(ga))
#define CP_COMMIT() asm volatile("cp.async.commit_group;")
#define CP_WAIT(n)  asm volatile("cp.async.wait_group %0;" :: "n"(n))

__device__ __forceinline__ void ldsm_x4(uint32_t& r0, uint32_t& r1, uint32_t& r2,
                                        uint32_t& r3, uint32_t addr) {
    asm volatile("ldmatrix.sync.aligned.m8n8.x4.shared.b16 {%0,%1,%2,%3}, [%4];"
                 : "=r"(r0), "=r"(r1), "=r"(r2), "=r"(r3) : "r"(addr));
}
__device__ __forceinline__ void ldsm_x2(uint32_t& r0, uint32_t& r1, uint32_t addr) {
    asm volatile("ldmatrix.sync.aligned.m8n8.x2.shared.b16 {%0,%1}, [%2];"
                 : "=r"(r0), "=r"(r1) : "r"(addr));
}

#define MMA16(d, a, b0, b1)                                                         \
    asm volatile("mma.sync.aligned.m16n8k16.row.col.f32.f16.f16.f32 "               \
                 "{%0,%1,%2,%3},{%4,%5,%6,%7},{%8,%9},{%0,%1,%2,%3};"               \
                 : "+f"((d)[0]), "+f"((d)[1]), "+f"((d)[2]), "+f"((d)[3])           \
                 : "r"((a)[0]), "r"((a)[1]), "r"((a)[2]), "r"((a)[3]),              \
                   "r"(b0), "r"(b1))

// read 4 channels (two half2) as floats
__device__ __forceinline__ float4 ld_scratch4(const __half* p) {
    uint2 u = *(const uint2*)p;
    float2 fa = __half22float2(*(__half2*)&u.x);
    float2 fb = __half22float2(*(__half2*)&u.y);
    return make_float4(fa.x, fa.y, fb.x, fb.y);
}
// read 8 channels as 8 floats via one 16B load
__device__ __forceinline__ void ld_scratch8(const __half* p, float* v) {
    uint4 u = *(const uint4*)p;
    float2 f0 = __half22float2(*(__half2*)&u.x);
    float2 f1 = __half22float2(*(__half2*)&u.y);
    float2 f2 = __half22float2(*(__half2*)&u.z);
    float2 f3 = __half22float2(*(__half2*)&u.w);
    v[0] = f0.x; v[1] = f0.y; v[2] = f1.x; v[3] = f1.y;
    v[4] = f2.x; v[5] = f2.y; v[6] = f3.x; v[7] = f3.y;
}

// ---------------- K_prep: W->fp16, x->fp16, pslot=-1, histogram, last-block prefix -----
__global__ void k_prep(const float* __restrict__ x, const float* __restrict__ W,
                       const int* __restrict__ offset, int N) {
    const int gsz = gridDim.x * blockDim.x;
    const int gid = blockIdx.x * blockDim.x + threadIdx.x;

    for (int i = gid; i < TAPS * C_IN * C_OUT; i += gsz) {
        int t = i / (C_IN * C_OUT);
        int r = i % (C_IN * C_OUT);
        int k = r >> 8, n = r & 255;
        g_Bth[t * C_OUT * C_IN + n * C_IN + k] = __float2half_rn(W[i]);
    }
    for (int i = gid; i < N * TAPS; i += gsz) g_pslot[i] = -1;

    const float4* x4 = (const float4*)x;
    uint4* xo = (uint4*)g_xh;
    for (int i = gid; i < N * (C_IN / 8); i += gsz) {
        float4 v0 = x4[i * 2], v1 = x4[i * 2 + 1];
        __half2 h0 = __floats2half2_rn(v0.x, v0.y);
        __half2 h1 = __floats2half2_rn(v0.z, v0.w);
        __half2 h2 = __floats2half2_rn(v1.x, v1.y);
        __half2 h3 = __floats2half2_rn(v1.z, v1.w);
        uint4 o;
        o.x = *(uint32_t*)&h0; o.y = *(uint32_t*)&h1;
        o.z = *(uint32_t*)&h2; o.w = *(uint32_t*)&h3;
        xo[i] = o;
    }
    int c0 = 0, c1 = 0, c2 = 0, c3 = 0;
    for (int i = gid; i < N; i += gsz) {
        int k = offset[i];
        c0 += (k == 0); c1 += (k == 1); c2 += (k == 2); c3 += (k == 3);
    }
    c0 = __reduce_add_sync(0xffffffffu, c0);
    c1 = __reduce_add_sync(0xffffffffu, c1);
    c2 = __reduce_add_sync(0xffffffffu, c2);
    c3 = __reduce_add_sync(0xffffffffu, c3);
    if ((threadIdx.x & 31) == 0) {
        atomicAdd(&g_tap_count[0], c0);
        atomicAdd(&g_tap_count[1], c1);
        atomicAdd(&g_tap_count[2], c2);
        atomicAdd(&g_tap_count[3], c3);
    }
    __syncthreads();
    if (threadIdx.x == 0) {
        __threadfence();
        int done = atomicAdd(&g_ctr, 1);
        if (done == (int)gridDim.x - 1) {
            g_ctr = 0;                     // reset for next replay
            int b = 0;
            for (int t = 0; t < TAPS; t++) {
                g_pad_base[t]   = b;
                g_tap_cursor[t] = b;
                b += (g_tap_count[t] + 127) & ~127;
            }
            g_pad_base[TAPS] = b;
        }
    }
}

// ---------------- K_perm: permutation + inverse slot map + active count ----------------
__global__ void k_perm(const int* __restrict__ offset, const int* __restrict__ out_index,
                       const float* __restrict__ mask, int N) {
    int lane = threadIdx.x & 31;
    float cm = 0.f;
    for (int i = blockIdx.x * blockDim.x + threadIdx.x; i < N;
         i += gridDim.x * blockDim.x) {
        int k = offset[i];
        unsigned grp = __match_any_sync(0xffffffffu, k);
        int leader   = __ffs(grp) - 1;
        int rank     = __popc(grp & ((1u << lane) - 1u));
        int base = 0;
        if (lane == leader) base = atomicAdd(&g_tap_cursor[k], __popc(grp));
        base = __shfl_sync(0xffffffffu, base, leader);
        int pos = base + rank;
        g_perm[pos] = i;
        g_pslot[(size_t)out_index[i] * TAPS + k] = pos;
        cm += mask[i];
    }
#pragma unroll
    for (int o = 16; o; o >>= 1) cm += __shfl_xor_sync(0xffffffffu, cm, o);
    if ((threadIdx.x & 31) == 0) atomicAdd(&g_cnt, cm);
}

// ---------------- K_conv: fp16 GEMM -> fp16 scratch (pads zeroed) + fused linear stats -
#define SMEM_BYTES (1024 + 6 * STAGE_B)

__global__ __launch_bounds__(256, 2)
void k_conv() {
    extern __shared__ char smc[];
    int*   srow   = (int*)smc;                     // 128 ints
    float* svalid = (float*)(smc + 512);           // 128 floats
    const uint32_t aBase = smem_u32(smc + 1024);   // 3 A stages
    const uint32_t bBase = aBase + 3 * STAGE_B;    // 3 B stages
    __shared__ float bsum[128], bsq[128];          // per-block column stats

    const int tid  = threadIdx.x;
    const int lane = tid & 31;
    const int wid  = tid >> 5;
    const int wm   = wid & 3;
    const int wn   = wid >> 2;
    const int p0   = (int)blockIdx.y * 128;
    if (p0 >= g_pad_base[TAPS]) return;

    int tap = 0;
#pragma unroll
    for (int t = 1; t < TAPS; t++)
        if (p0 >= g_pad_base[t]) tap = t;

    const int colStart = (int)blockIdx.x * 128;
    const __half* Bth = g_Bth + (size_t)tap * (C_OUT * C_IN);

    if (tid < 128) {
        int pos = p0 + tid;
        srow[tid]   = g_perm[pos];   // stale for pads; in-bounds, masked at store
        svalid[tid] = (pos - g_pad_base[tap] < g_tap_count[tap]) ? 1.f : 0.f;
        bsum[tid] = 0.f;
        bsq[tid]  = 0.f;
    }
    __syncthreads();

    float acc[2][8][4];
#pragma unroll
    for (int i = 0; i < 2; i++)
#pragma unroll
        for (int j = 0; j < 8; j++)
#pragma unroll
            for (int q = 0; q < 4; q++) acc[i][j][q] = 0.f;

    // logical 16B-chunk q of row r stored at chunk (q ^ ((r>>1)&3))
#define LOAD_CHUNK(c)                                                               \
    do {                                                                            \
        const int _k0 = (c) * 32, _st = (c) % 3;                                    \
        _Pragma("unroll")                                                           \
        for (int _u = 0; _u < 2; _u++) {                                            \
            int _seg = _u * 256 + tid;                                              \
            int _row = _seg >> 2, _q = _seg & 3;                                    \
            const __half* _ga = g_xh + (size_t)srow[_row] * C_IN + _k0 + _q * 8;    \
            uint32_t _da = aBase + _st * STAGE_B + _row * 64 +                      \
                           ((_q ^ ((_row >> 1) & 3)) << 4);                         \
            CP_ASYNC(_da, _ga);                                                     \
        }                                                                           \
        _Pragma("unroll")                                                           \
        for (int _u = 0; _u < 2; _u++) {                                            \
            int _seg = _u * 256 + tid;                                              \
            int _n = _seg >> 2, _q = _seg & 3;                                      \
            const __half* _gb = Bth + (size_t)(colStart + _n) * C_IN + _k0 + _q * 8;\
            uint32_t _db = bBase + _st * STAGE_B + _n * 64 +                        \
                           ((_q ^ ((_n >> 1) & 3)) << 4);                           \
            CP_ASYNC(_db, _gb);                                                     \
        }                                                                           \
        CP_COMMIT();                                                                \
    } while (0)

#define COMPUTE(c)                                                                  \
    do {                                                                            \
        const uint32_t aSt = aBase + ((c) % 3) * STAGE_B;                           \
        const uint32_t bSt = bBase + ((c) % 3) * STAGE_B;                           \
        _Pragma("unroll")                                                           \
        for (int ks = 0; ks < 2; ks++) {                                            \
            const int kc = ks * 2;                                                  \
            uint32_t a[2][4];                                                       \
            _Pragma("unroll")                                                       \
            for (int i = 0; i < 2; i++) {                                           \
                int row = wm * 32 + i * 16 + (lane & 15);                           \
                int cch = kc + (lane >> 4);                                         \
                uint32_t ad = aSt + row * 64 + ((cch ^ ((row >> 1) & 3)) << 4);     \
                ldsm_x4(a[i][0], a[i][1], a[i][2], a[i][3], ad);                    \
            }                                                                       \
            _Pragma("unroll")                                                       \
            for (int j = 0; j < 8; j++) {                                           \
                int row = wn * 64 + j * 8 + (lane & 7);                             \
                int cch = kc + ((lane >> 3) & 1);                                   \
                uint32_t bd = bSt + row * 64 + ((cch ^ ((row >> 1) & 3)) << 4);     \
                uint32_t b0, b1;                                                    \
                ldsm_x2(b0, b1, bd);                                                \
                MMA16(acc[0][j], a[0], b0, b1);                                     \
                MMA16(acc[1][j], a[1], b0, b1);                                     \
            }                                                                       \
        }                                                                           \
    } while (0)

    LOAD_CHUNK(0);
    LOAD_CHUNK(1);

    LOAD_CHUNK(2);
    CP_WAIT(2); __syncthreads();
    COMPUTE(0); __syncthreads();

    LOAD_CHUNK(3);
    CP_WAIT(2); __syncthreads();
    COMPUTE(1);

    CP_WAIT(1); __syncthreads();
    COMPUTE(2);

    CP_WAIT(0); __syncthreads();
    COMPUTE(3);

    // ---- epilogue: masked fp16 stores (coalesced) + fused linear stats from
    //      the ROUNDED values (bit-consistent with k_corr / k_final) ----
    const int lr0 = wm * 32 + (lane >> 2);
    const float f00 = svalid[lr0],      f01 = svalid[lr0 + 8];
    const float f10 = svalid[lr0 + 16], f11 = svalid[lr0 + 24];
#pragma unroll
    for (int j = 0; j < 8; j++) {
        const int cl = wn * 64 + j * 8 + (lane & 3) * 2;
        const int cg = colStart + cl;
        float s0 = 0.f, s1 = 0.f, q0 = 0.f, q1 = 0.f;
#pragma unroll
        for (int i = 0; i < 2; i++) {
            const float fa = (i == 0) ? f00 : f10;
            const float fb = (i == 0) ? f01 : f11;
            int rp = p0 + lr0 + i * 16;
            __half2 h01 = __floats2half2_rn(acc[i][j][0] * fa, acc[i][j][1] * fa);
            __half2 h23 = __floats2half2_rn(acc[i][j][2] * fb, acc[i][j][3] * fb);
            *(__half2*)&g_scratch[(size_t)rp * C_OUT + cg] = h01;
            *(__half2*)&g_scratch[(size_t)(rp + 8) * C_OUT + cg] = h23;
            float2 r01 = __half22float2(h01);
            float2 r23 = __half22float2(h23);
            s0 += r01.x + r23.x;
            s1 += r01.y + r23.y;
            q0 += r01.x * r01.x + r23.x * r23.x;
            q1 += r01.y * r01.y + r23.y * r23.y;
        }
        atomicAdd(&bsum[cl],     s0);
        atomicAdd(&bsum[cl + 1], s1);
        atomicAdd(&bsq[cl],      q0);
        atomicAdd(&bsq[cl + 1],  q1);
    }
    __syncthreads();
    if (tid < 128) {
        atomicAdd(&g_sum[colStart + tid],   bsum[tid]);
        atomicAdd(&g_sumsq[colStart + tid], bsq[tid]);
    }
#undef LOAD_CHUNK
#undef COMPUTE
}

// ---------------- K_corr: quadratic sumsq fix-up, multi-contributor sites only ---------
__global__ __launch_bounds__(256)
void k_corr(int N) {
    __shared__ float ssq[C_OUT];
    const int tid  = threadIdx.x;
    const int lane = tid & 31;
    const int g    = tid >> 5;
    const int s0   = blockIdx.x * 128;

    ssq[tid] = 0.f;
    __syncthreads();

    for (int it = 0; it < 16; it++) {
        int site = s0 + it * 8 + g;
        if (site >= N) continue;
        int4 ps = *(const int4*)&g_pslot[(size_t)site * TAPS];
        int cnt = (ps.x >= 0) + (ps.y >= 0) + (ps.z >= 0) + (ps.w >= 0);
        if (cnt < 2) continue;
        const int p[4] = {ps.x, ps.y, ps.z, ps.w};
        float v[8], q[8];
#pragma unroll
        for (int c = 0; c < 8; c++) { v[c] = 0.f; q[c] = 0.f; }
#pragma unroll
        for (int t = 0; t < TAPS; t++) {
            if (p[t] < 0) continue;
            float u[8];
            ld_scratch8(g_scratch + (size_t)p[t] * C_OUT + lane * 8, u);
#pragma unroll
            for (int c = 0; c < 8; c++) { v[c] += u[c]; q[c] += u[c] * u[c]; }
        }
#pragma unroll
        for (int c = 0; c < 8; c++)
            atomicAdd(&ssq[lane * 8 + c], v[c] * v[c] - q[c]);
    }
    __syncthreads();
    atomicAdd(&g_sumsq[tid], ssq[tid]);
}

// ---------------- K_bn ----------------
__global__ void k_bn(const float* __restrict__ gamma, const float* __restrict__ beta) {
    int c = threadIdx.x;
    float cnt  = g_cnt;
    float mean = g_sum[c] / cnt;
    float var  = fmaxf(g_sumsq[c] / cnt - mean * mean, 0.f);
    float sc   = rsqrtf(var + BN_EPS) * gamma[c];
    float bi   = beta[c] - mean * sc;
    g_scale[c] = sc;
    g_bias[c]  = bi;
    g_sum[c]   = 0.f;
    g_sumsq[c] = 0.f;
    if (c == 0) g_cnt = 0.f;
    if (c < TAPS) g_tap_count[c] = 0;
}

// ---------------- K_final: recombine + BN + ReLU + mask -> y ----------------
#define SITES_PER_BLOCK 256
__global__ __launch_bounds__(256)
void k_final(float* __restrict__ y, const float* __restrict__ mask, int N) {
    __shared__ int sp[SITES_PER_BLOCK * TAPS];
    const int tid = threadIdx.x;
    const int s0  = blockIdx.x * SITES_PER_BLOCK;

    for (int i = tid; i < SITES_PER_BLOCK * TAPS; i += 256) {
        int site = s0 + (i >> 2);
        sp[i] = (site < N) ? g_pslot[(size_t)site * TAPS + (i & 3)] : -1;
    }
    __syncthreads();

    const int c4 = tid & 63, sr = tid >> 6;
    const float4 sc = *(const float4*)&g_scale[c4 * 4];
    const float4 bi = *(const float4*)&g_bias[c4 * 4];

    for (int it = 0; it < SITES_PER_BLOCK / 4; it++) {
        int sl = it * 4 + sr;
        int site = s0 + sl;
        if (site >= N) continue;
        float4 v = make_float4(0.f, 0.f, 0.f, 0.f);
#pragma unroll
        for (int t = 0; t < TAPS; t++) {
            int p = sp[sl * 4 + t];
            if (p >= 0) {
                float4 u = ld_scratch4(g_scratch + (size_t)p * C_OUT + c4 * 4);
                v.x += u.x; v.y += u.y; v.z += u.z; v.w += u.w;
            }
        }
        float m = mask[site];
        v.x = fmaxf(fmaf(v.x, sc.x, bi.x), 0.f) * m;
        v.y = fmaxf(fmaf(v.y, sc.y, bi.y), 0.f) * m;
        v.z = fmaxf(fmaf(v.z, sc.z, bi.z), 0.f) * m;
        v.w = fmaxf(fmaf(v.w, sc.w, bi.w), 0.f) * m;
        *(float4*)&y[(size_t)site * C_OUT + c4 * 4] = v;
    }
}

// ---------------- launch ----------------
extern "C" void kernel_launch(void* const* d_in, const int* in_sizes, int n_in,
                              void* d_out, int out_size) {
    const float* x         = (const float*)d_in[0];
    const float* W         = (const float*)d_in[1];
    const float* gamma     = (const float*)d_in[2];
    const float* beta      = (const float*)d_in[3];
    const int*   offset    = (const int*)d_in[4];
    const int*   out_index = (const int*)d_in[5];
    const float* mask      = (const float*)d_in[6];
    float*       out       = (float*)d_out;

    int N = in_sizes[4];
    if (N > N_MAX) N = N_MAX;

    cudaFuncSetAttribute(k_conv, cudaFuncAttributeMaxDynamicSharedMemorySize,
                         SMEM_BYTES);

    k_prep<<<512, 256>>>(x, W, offset, N);                                  // 0
    k_perm<<<256, 256>>>(offset, out_index, mask, N);                       // 1

    int tiles = (N + 127) / 128 + TAPS;   // upper bound incl. per-tap padding
    k_conv<<<dim3(2, tiles), 256, SMEM_BYTES>>>();                          // 2

    int cb = (N + 127) / 128;
    k_corr<<<cb, 256>>>(N);                                                 // 3
    k_bn<<<1, 256>>>(gamma, beta);                                          // 4
    int fb = (N + SITES_PER_BLOCK - 1) / SITES_PER_BLOCK;
    k_final<<<fb, 256>>>(out, mask, N);                                     // 5  <- ncu -s 5
}

// round 14
// speedup vs baseline: 1.7709x; 1.7709x over previous
#include <cuda_runtime.h>
#include <cuda_fp16.h>
#include <cstdint>

#define C_IN   128
#define C_OUT  256
#define TAPS   4
#define N_MAX  262144
#define PADN_MAX (N_MAX + TAPS * 128)
#define BN_EPS 1e-4f
#define STAGE_B 8192               // one A or B stage: 128 rows x 64 bytes (32 fp16)

// ---------------- device scratch ----------------
__device__ __half g_scratch[(size_t)PADN_MAX * C_OUT];  // contributions, fp16, perm order
__device__ __half g_xh[(size_t)N_MAX * C_IN];           // x converted to fp16
__device__ __half g_Bth[TAPS * C_OUT * C_IN];           // W as [tap][n][k], fp16
__device__ int   g_pslot[N_MAX * TAPS];                 // pslot[site*4+tap] = perm pos or -1
__device__ int   g_perm[PADN_MAX];                      // perm position -> input row
__device__ int   g_tap_count[TAPS];
__device__ int   g_pad_base[TAPS + 1];
__device__ int   g_tap_cursor[TAPS];
__device__ float g_sum[C_OUT];
__device__ float g_sumsq[C_OUT];
__device__ float g_cnt;
__device__ float g_scale[C_OUT];
__device__ float g_bias[C_OUT];

// ---------------- helpers ----------------
__device__ __forceinline__ uint32_t smem_u32(const void* p) {
    uint32_t a;
    asm("{ .reg .u64 t; cvta.to.shared.u64 t, %1; cvt.u32.u64 %0, t; }" : "=r"(a) : "l"(p));
    return a;
}

#define CP_ASYNC(sa, ga) \
    asm volatile("cp.async.cg.shared.global [%0], [%1], 16;" :: "r"(sa), "l"(ga))
#define CP_COMMIT() asm volatile("cp.async.commit_group;")
#define CP_WAIT(n)  asm volatile("cp.async.wait_group %0;" :: "n"(n))

__device__ __forceinline__ void ldsm_x4(uint32_t& r0, uint32_t& r1, uint32_t& r2,
                                        uint32_t& r3, uint32_t addr) {
    asm volatile("ldmatrix.sync.aligned.m8n8.x4.shared.b16 {%0,%1,%2,%3}, [%4];"
                 : "=r"(r0), "=r"(r1), "=r"(r2), "=r"(r3) : "r"(addr));
}
__device__ __forceinline__ void ldsm_x2(uint32_t& r0, uint32_t& r1, uint32_t addr) {
    asm volatile("ldmatrix.sync.aligned.m8n8.x2.shared.b16 {%0,%1}, [%2];"
                 : "=r"(r0), "=r"(r1) : "r"(addr));
}

#define MMA16(d, a, b0, b1)                                                         \
    asm volatile("mma.sync.aligned.m16n8k16.row.col.f32.f16.f16.f32 "               \
                 "{%0,%1,%2,%3},{%4,%5,%6,%7},{%8,%9},{%0,%1,%2,%3};"               \
                 : "+f"((d)[0]), "+f"((d)[1]), "+f"((d)[2]), "+f"((d)[3])           \
                 : "r"((a)[0]), "r"((a)[1]), "r"((a)[2]), "r"((a)[3]),              \
                   "r"(b0), "r"(b1))

// read 4 channels (two half2) as floats
__device__ __forceinline__ float4 ld_scratch4(const __half* p) {
    uint2 u = *(const uint2*)p;
    float2 fa = __half22float2(*(__half2*)&u.x);
    float2 fb = __half22float2(*(__half2*)&u.y);
    return make_float4(fa.x, fa.y, fb.x, fb.y);
}

// ---------------- K_prep: W->fp16 transpose, x->fp16 stream, tap histogram ------------
__global__ void k_prep(const float* __restrict__ x, const float* __restrict__ W,
                       const int* __restrict__ offset, int N) {
    const int gsz = gridDim.x * blockDim.x;
    const int gid = blockIdx.x * blockDim.x + threadIdx.x;

    for (int i = gid; i < TAPS * C_IN * C_OUT; i += gsz) {
        int t = i / (C_IN * C_OUT);
        int r = i % (C_IN * C_OUT);
        int k = r >> 8, n = r & 255;
        g_Bth[t * C_OUT * C_IN + n * C_IN + k] = __float2half_rn(W[i]);
    }
    const float4* x4 = (const float4*)x;
    uint4* xo = (uint4*)g_xh;
    for (int i = gid; i < N * (C_IN / 8); i += gsz) {
        float4 v0 = x4[i * 2], v1 = x4[i * 2 + 1];
        __half2 h0 = __floats2half2_rn(v0.x, v0.y);
        __half2 h1 = __floats2half2_rn(v0.z, v0.w);
        __half2 h2 = __floats2half2_rn(v1.x, v1.y);
        __half2 h3 = __floats2half2_rn(v1.z, v1.w);
        uint4 o;
        o.x = *(uint32_t*)&h0; o.y = *(uint32_t*)&h1;
        o.z = *(uint32_t*)&h2; o.w = *(uint32_t*)&h3;
        xo[i] = o;
    }
    int c0 = 0, c1 = 0, c2 = 0, c3 = 0;
    for (int i = gid; i < N; i += gsz) {
        int k = offset[i];
        c0 += (k == 0); c1 += (k == 1); c2 += (k == 2); c3 += (k == 3);
    }
    c0 = __reduce_add_sync(0xffffffffu, c0);
    c1 = __reduce_add_sync(0xffffffffu, c1);
    c2 = __reduce_add_sync(0xffffffffu, c2);
    c3 = __reduce_add_sync(0xffffffffu, c3);
    if ((threadIdx.x & 31) == 0) {
        atomicAdd(&g_tap_count[0], c0);
        atomicAdd(&g_tap_count[1], c1);
        atomicAdd(&g_tap_count[2], c2);
        atomicAdd(&g_tap_count[3], c3);
    }
}

// ---------------- K_prefix ----------------
__global__ void k_prefix() {
    if (threadIdx.x == 0 && blockIdx.x == 0) {
        int b = 0;
        for (int t = 0; t < TAPS; t++) {
            g_pad_base[t]   = b;
            g_tap_cursor[t] = b;
            b += (g_tap_count[t] + 127) & ~127;
        }
        g_pad_base[TAPS] = b;
    }
}

// ---------------- K_perm: permutation + inverse slot map + active count ----------------
__global__ void k_perm(const int* __restrict__ offset, const int* __restrict__ out_index,
                       const float* __restrict__ mask, int N) {
    int lane = threadIdx.x & 31;
    float cm = 0.f;
    for (int i = blockIdx.x * blockDim.x + threadIdx.x; i < N;
         i += gridDim.x * blockDim.x) {
        int k = offset[i];
        unsigned grp = __match_any_sync(0xffffffffu, k);
        int leader   = __ffs(grp) - 1;
        int rank     = __popc(grp & ((1u << lane) - 1u));
        int base = 0;
        if (lane == leader) base = atomicAdd(&g_tap_cursor[k], __popc(grp));
        base = __shfl_sync(0xffffffffu, base, leader);
        int pos = base + rank;
        g_perm[pos] = i;
        g_pslot[(size_t)out_index[i] * TAPS + k] = pos;
        cm += mask[i];
    }
#pragma unroll
    for (int o = 16; o; o >>= 1) cm += __shfl_xor_sync(0xffffffffu, cm, o);
    if ((threadIdx.x & 31) == 0) atomicAdd(&g_cnt, cm);
}

// ---------------- K_conv: fp16 GEMM, TWO row-tiles per block, continuous pipeline ------
// XOR-swizzled 64B-row tiles; 3 stages over 8 chunks (2 tiles x 4 K-chunks).
#define SMEM_BYTES (1024 + 6 * STAGE_B)

__global__ __launch_bounds__(256, 2)
void k_conv() {
    extern __shared__ char smc[];
    int* srowA = (int*)smc;                        // 128 ints
    int* srowB = (int*)smc + 128;                  // 128 ints
    const uint32_t aBase = smem_u32(smc + 1024);   // 3 A stages
    const uint32_t bBase = aBase + 3 * STAGE_B;    // 3 B stages

    const int tid  = threadIdx.x;
    const int lane = tid & 31;
    const int wid  = tid >> 5;
    const int wm   = wid & 3;
    const int wn   = wid >> 2;
    const int padN = g_pad_base[TAPS];
    const int p0a  = (int)blockIdx.y * 256;
    if (p0a >= padN) return;
    const int p0b  = p0a + 128;
    const bool hasB = (p0b < padN);

    int tapA = 0, tapB = 0;
#pragma unroll
    for (int t = 1; t < TAPS; t++) {
        if (p0a >= g_pad_base[t]) tapA = t;
        if (p0b >= g_pad_base[t]) tapB = t;
    }

    const int colStart = (int)blockIdx.x * 128;
    const __half* BthA = g_Bth + (size_t)tapA * (C_OUT * C_IN);
    const __half* BthB = g_Bth + (size_t)tapB * (C_OUT * C_IN);

    if (tid < 128) {
        srowA[tid] = g_perm[p0a + tid];            // pad slots: stale, unused downstream
    } else {
        srowB[tid - 128] = hasB ? g_perm[p0b + tid - 128] : 0;
    }
    __syncthreads();

    float acc[2][8][4];
#pragma unroll
    for (int i = 0; i < 2; i++)
#pragma unroll
        for (int j = 0; j < 8; j++)
#pragma unroll
            for (int q = 0; q < 4; q++) acc[i][j][q] = 0.f;

    // logical 16B-chunk q of row r stored at chunk (q ^ ((r>>1)&3))
#define LOAD_CHUNK(c, SR, BT)                                                       \
    do {                                                                            \
        const int _k0 = ((c) & 3) * 32, _st = (c) % 3;                              \
        _Pragma("unroll")                                                           \
        for (int _u = 0; _u < 2; _u++) {                                            \
            int _seg = _u * 256 + tid;                                              \
            int _row = _seg >> 2, _q = _seg & 3;                                    \
            const __half* _ga = g_xh + (size_t)(SR)[_row] * C_IN + _k0 + _q * 8;    \
            uint32_t _da = aBase + _st * STAGE_B + _row * 64 +                      \
                           ((_q ^ ((_row >> 1) & 3)) << 4);                         \
            CP_ASYNC(_da, _ga);                                                     \
        }                                                                           \
        _Pragma("unroll")                                                           \
        for (int _u = 0; _u < 2; _u++) {                                            \
            int _seg = _u * 256 + tid;                                              \
            int _n = _seg >> 2, _q = _seg & 3;                                      \
            const __half* _gb = (BT) + (size_t)(colStart + _n) * C_IN + _k0 + _q * 8;\
            uint32_t _db = bBase + _st * STAGE_B + _n * 64 +                        \
                           ((_q ^ ((_n >> 1) & 3)) << 4);                           \
            CP_ASYNC(_db, _gb);                                                     \
        }                                                                           \
        CP_COMMIT();                                                                \
    } while (0)

#define COMPUTE(c)                                                                  \
    do {                                                                            \
        const uint32_t aSt = aBase + ((c) % 3) * STAGE_B;                           \
        const uint32_t bSt = bBase + ((c) % 3) * STAGE_B;                           \
        _Pragma("unroll")                                                           \
        for (int ks = 0; ks < 2; ks++) {                                            \
            const int kc = ks * 2;                                                  \
            uint32_t a[2][4];                                                       \
            _Pragma("unroll")                                                       \
            for (int i = 0; i < 2; i++) {                                           \
                int row = wm * 32 + i * 16 + (lane & 15);                           \
                int cch = kc + (lane >> 4);                                         \
                uint32_t ad = aSt + row * 64 + ((cch ^ ((row >> 1) & 3)) << 4);     \
                ldsm_x4(a[i][0], a[i][1], a[i][2], a[i][3], ad);                    \
            }                                                                       \
            _Pragma("unroll")                                                       \
            for (int j = 0; j < 8; j++) {                                           \
                int row = wn * 64 + j * 8 + (lane & 7);                             \
                int cch = kc + ((lane >> 3) & 1);                                   \
                uint32_t bd = bSt + row * 64 + ((cch ^ ((row >> 1) & 3)) << 4);     \
                uint32_t b0, b1;                                                    \
                ldsm_x2(b0, b1, bd);                                                \
                MMA16(acc[0][j], a[0], b0, b1);                                     \
                MMA16(acc[1][j], a[1], b0, b1);                                     \
            }                                                                       \
        }                                                                           \
    } while (0)

#define EPILOGUE(P0)                                                                \
    do {                                                                            \
        _Pragma("unroll")                                                           \
        for (int i = 0; i < 2; i++) {                                               \
            _Pragma("unroll")                                                       \
            for (int j = 0; j < 8; j++) {                                           \
                int rp = (P0) + wm * 32 + i * 16 + (lane >> 2);                     \
                int cg = colStart + wn * 64 + j * 8 + (lane & 3) * 2;               \
                __half2 h01 = __floats2half2_rn(acc[i][j][0], acc[i][j][1]);        \
                __half2 h23 = __floats2half2_rn(acc[i][j][2], acc[i][j][3]);        \
                *(__half2*)&g_scratch[(size_t)rp * C_OUT + cg] = h01;               \
                *(__half2*)&g_scratch[(size_t)(rp + 8) * C_OUT + cg] = h23;         \
            }                                                                       \
        }                                                                           \
    } while (0)

    // continuous 8-chunk pipeline across both tiles
    LOAD_CHUNK(0, srowA, BthA);
    LOAD_CHUNK(1, srowA, BthA);
    LOAD_CHUNK(2, srowA, BthA);

    CP_WAIT(2); __syncthreads();
    COMPUTE(0); __syncthreads();
    LOAD_CHUNK(3, srowA, BthA);

    CP_WAIT(2); __syncthreads();
    COMPUTE(1); __syncthreads();
    LOAD_CHUNK(4, srowB, BthB);

    CP_WAIT(2); __syncthreads();
    COMPUTE(2); __syncthreads();
    LOAD_CHUNK(5, srowB, BthB);

    CP_WAIT(2); __syncthreads();
    COMPUTE(3);
    EPILOGUE(p0a);                 // tile A done; stores overlap tile B loads
#pragma unroll
    for (int i = 0; i < 2; i++)
#pragma unroll
        for (int j = 0; j < 8; j++)
#pragma unroll
            for (int q = 0; q < 4; q++) acc[i][j][q] = 0.f;
    __syncthreads();
    LOAD_CHUNK(6, srowB, BthB);

    CP_WAIT(2); __syncthreads();
    COMPUTE(4); __syncthreads();
    LOAD_CHUNK(7, srowB, BthB);

    CP_WAIT(2); __syncthreads();
    COMPUTE(5);

    CP_WAIT(1); __syncthreads();
    COMPUTE(6);

    CP_WAIT(0); __syncthreads();
    COMPUTE(7);

    if (hasB) EPILOGUE(p0b);
#undef LOAD_CHUNK
#undef COMPUTE
#undef EPILOGUE
}

// ---------------- K_cstats: combine (discard) + per-channel stats (R12 version) --------
#define SITES_PER_BLOCK 256
__global__ __launch_bounds__(256)
void k_cstats(int N) {
    __shared__ int   sp[SITES_PER_BLOCK * TAPS];   // 4 KB
    __shared__ float ssum[C_OUT], ssq[C_OUT];
    const int tid = threadIdx.x;
    const int s0  = blockIdx.x * SITES_PER_BLOCK;

    for (int i = tid; i < C_OUT; i += 256) { ssum[i] = 0.f; ssq[i] = 0.f; }
    for (int i = tid; i < SITES_PER_BLOCK * TAPS; i += 256) {
        int site = s0 + (i >> 2);
        sp[i] = (site < N) ? g_pslot[(size_t)site * TAPS + (i & 3)] : -1;
    }
    __syncthreads();

    const int c4 = tid & 63, sr = tid >> 6;
    float ls0 = 0.f, ls1 = 0.f, ls2 = 0.f, ls3 = 0.f;
    float lq0 = 0.f, lq1 = 0.f, lq2 = 0.f, lq3 = 0.f;

    for (int it = 0; it < SITES_PER_BLOCK / 4; it++) {
        int sl = it * 4 + sr;
        float4 v = make_float4(0.f, 0.f, 0.f, 0.f);
#pragma unroll
        for (int t = 0; t < TAPS; t++) {
            int p = sp[sl * 4 + t];
            if (p >= 0) {
                float4 u = ld_scratch4(g_scratch + (size_t)p * C_OUT + c4 * 4);
                v.x += u.x; v.y += u.y; v.z += u.z; v.w += u.w;
            }
        }
        ls0 += v.x; ls1 += v.y; ls2 += v.z; ls3 += v.w;
        lq0 += v.x * v.x; lq1 += v.y * v.y; lq2 += v.z * v.z; lq3 += v.w * v.w;
    }
    atomicAdd(&ssum[c4 * 4 + 0], ls0);
    atomicAdd(&ssum[c4 * 4 + 1], ls1);
    atomicAdd(&ssum[c4 * 4 + 2], ls2);
    atomicAdd(&ssum[c4 * 4 + 3], ls3);
    atomicAdd(&ssq[c4 * 4 + 0], lq0);
    atomicAdd(&ssq[c4 * 4 + 1], lq1);
    atomicAdd(&ssq[c4 * 4 + 2], lq2);
    atomicAdd(&ssq[c4 * 4 + 3], lq3);
    __syncthreads();
    for (int i = tid; i < C_OUT; i += 256) {
        atomicAdd(&g_sum[i], ssum[i]);
        atomicAdd(&g_sumsq[i], ssq[i]);
    }
}

// ---------------- K_bn ----------------
__global__ void k_bn(const float* __restrict__ gamma, const float* __restrict__ beta) {
    int c = threadIdx.x;
    float cnt  = g_cnt;
    float mean = g_sum[c] / cnt;
    float var  = fmaxf(g_sumsq[c] / cnt - mean * mean, 0.f);
    float sc   = rsqrtf(var + BN_EPS) * gamma[c];
    float bi   = beta[c] - mean * sc;
    g_scale[c] = sc;
    g_bias[c]  = bi;
    g_sum[c]   = 0.f;
    g_sumsq[c] = 0.f;
    if (c == 0) g_cnt = 0.f;
    if (c < TAPS) g_tap_count[c] = 0;
}

// ---------------- K_final: recombine + BN + ReLU + mask -> y (R12 version) -------------
__global__ __launch_bounds__(256)
void k_final(float* __restrict__ y, const float* __restrict__ mask, int N) {
    __shared__ int sp[SITES_PER_BLOCK * TAPS];
    const int tid = threadIdx.x;
    const int s0  = blockIdx.x * SITES_PER_BLOCK;

    for (int i = tid; i < SITES_PER_BLOCK * TAPS; i += 256) {
        int site = s0 + (i >> 2);
        sp[i] = (site < N) ? g_pslot[(size_t)site * TAPS + (i & 3)] : -1;
    }
    __syncthreads();

    const int c4 = tid & 63, sr = tid >> 6;
    const float4 sc = *(const float4*)&g_scale[c4 * 4];
    const float4 bi = *(const float4*)&g_bias[c4 * 4];

    for (int it = 0; it < SITES_PER_BLOCK / 4; it++) {
        int sl = it * 4 + sr;
        int site = s0 + sl;
        if (site >= N) continue;
        float4 v = make_float4(0.f, 0.f, 0.f, 0.f);
#pragma unroll
        for (int t = 0; t < TAPS; t++) {
            int p = sp[sl * 4 + t];
            if (p >= 0) {
                float4 u = ld_scratch4(g_scratch + (size_t)p * C_OUT + c4 * 4);
                v.x += u.x; v.y += u.y; v.z += u.z; v.w += u.w;
            }
        }
        float m = mask[site];
        v.x = fmaxf(fmaf(v.x, sc.x, bi.x), 0.f) * m;
        v.y = fmaxf(fmaf(v.y, sc.y, bi.y), 0.f) * m;
        v.z = fmaxf(fmaf(v.z, sc.z, bi.z), 0.f) * m;
        v.w = fmaxf(fmaf(v.w, sc.w, bi.w), 0.f) * m;
        *(float4*)&y[(size_t)site * C_OUT + c4 * 4] = v;
    }
}

// ---------------- launch ----------------
extern "C" void kernel_launch(void* const* d_in, const int* in_sizes, int n_in,
                              void* d_out, int out_size) {
    const float* x         = (const float*)d_in[0];
    const float* W         = (const float*)d_in[1];
    const float* gamma     = (const float*)d_in[2];
    const float* beta      = (const float*)d_in[3];
    const int*   offset    = (const int*)d_in[4];
    const int*   out_index = (const int*)d_in[5];
    const float* mask      = (const float*)d_in[6];
    float*       out       = (float*)d_out;

    int N = in_sizes[4];
    if (N > N_MAX) N = N_MAX;

    cudaFuncSetAttribute(k_conv, cudaFuncAttributeMaxDynamicSharedMemorySize,
                         SMEM_BYTES);

    void* pslotPtr = nullptr;
    cudaGetSymbolAddress(&pslotPtr, g_pslot);

    cudaMemsetAsync(pslotPtr, 0xFF, sizeof(int) * (size_t)N_MAX * TAPS);   // 0

    k_prep<<<512, 256>>>(x, W, offset, N);                                  // 1
    k_prefix<<<1, 32>>>();                                                  // 2
    k_perm<<<256, 256>>>(offset, out_index, mask, N);                       // 3

    int tiles = (N + 127) / 128 + TAPS;   // upper bound incl. per-tap padding
    int pairTiles = (tiles + 1) / 2;
    k_conv<<<dim3(2, pairTiles), 256, SMEM_BYTES>>>();                      // 4

    int cb = (N + SITES_PER_BLOCK - 1) / SITES_PER_BLOCK;
    k_cstats<<<cb, 256>>>(N);                                               // 5  <- ncu -s 5
    k_bn<<<1, 256>>>(gamma, beta);                                          // 6
    k_final<<<cb, 256>>>(out, mask, N);                                     // 7
}